// round 2
// baseline (speedup 1.0000x reference)
#include <cuda_runtime.h>
#include <math.h>

// ---------------------------------------------------------------------------
// Scratch (no allocations allowed -> static __device__ arrays)
// ---------------------------------------------------------------------------
__device__ float g_h1[256 * 3 * 50625];  // [B,3,15,15,15,15]
__device__ float g_h2[256 * 3 * 20736];  // [B,3,12,12,12,12]
__device__ float g_h3[256 * 4 * 6561];   // [B,4,9,9,9,9]
__device__ float g_h4[256 * 5 * 1296];   // [B,5,6,6,6,6]
__device__ float g_h5[256 * 5 * 256];    // [B,5,4,4,4,4] == [B,1280]

// ---------------------------------------------------------------------------
// Generic 4D conv + bias + relu (valid padding, stride 1).
//   in : [B, CIN, S, S, S, S]
//   w  : [COUT, CIN, K, K, K, K]
//   out: [B, COUT, T, T, T, T],  T = S-K+1
// Block = one (b, ow). Per ci: stage slab in[b,ci,ow..ow+K-1,:,:,:] into smem
// (z-rows padded to odd stride -> conflict-free LDS across oy lanes).
// Thread = one (ox,oy); accumulates all COUT x T outputs in registers.
// ---------------------------------------------------------------------------
template <int S, int K, int CIN, int COUT>
__global__ void conv4d_relu(const float* __restrict__ x,
                            const float* __restrict__ w,
                            const float* __restrict__ bias,
                            float* __restrict__ y)
{
    constexpr int T  = S - K + 1;
    constexpr int RS = (S & 1) ? S : S + 1;   // padded z-row stride (odd)
    constexpr int S3 = S * S * S;
    constexpr int WN = COUT * CIN * K * K * K * K;

    extern __shared__ float sm[];
    float* sw   = sm;          // [WN] weights
    float* slab = sm + WN;     // [K*S*S*RS] one input channel slab

    const int tid = threadIdx.x;
    const int b   = blockIdx.x / T;
    const int ow  = blockIdx.x % T;

    for (int i = tid; i < WN; i += blockDim.x) sw[i] = w[i];

    float acc[COUT][T];
#pragma unroll
    for (int co = 0; co < COUT; ++co)
#pragma unroll
        for (int oz = 0; oz < T; ++oz) acc[co][oz] = 0.f;

    const int  ox     = tid / T;
    const int  oy     = tid % T;
    const bool active = (tid < T * T);

    for (int ci = 0; ci < CIN; ++ci) {
        __syncthreads();   // protect slab from previous iteration's readers
        const float* src = x + ((size_t)(b * CIN + ci) * S + ow) * S3;
        for (int i = tid; i < K * S3; i += blockDim.x) {
            int kw = i / S3;
            int r  = i - kw * S3;
            int xx = r / (S * S);
            int r2 = r - xx * (S * S);
            int yy = r2 / S;
            int zz = r2 - yy * S;
            slab[((kw * S + xx) * S + yy) * RS + zz] = src[i];
        }
        __syncthreads();

        if (active) {
#pragma unroll 1
            for (int kw = 0; kw < K; ++kw)
#pragma unroll 1
            for (int kx = 0; kx < K; ++kx)
#pragma unroll 1
            for (int ky = 0; ky < K; ++ky) {
                const float* row = &slab[((kw * S + ox + kx) * S + oy + ky) * RS];
                float r[S];
#pragma unroll
                for (int z = 0; z < S; ++z) r[z] = row[z];

                float wr[COUT][K];
#pragma unroll
                for (int co = 0; co < COUT; ++co)
#pragma unroll
                    for (int kz = 0; kz < K; ++kz)
                        wr[co][kz] =
                            sw[((((co * CIN + ci) * K + kw) * K + kx) * K + ky) * K + kz];

#pragma unroll
                for (int oz = 0; oz < T; ++oz)
#pragma unroll
                    for (int co = 0; co < COUT; ++co)
#pragma unroll
                        for (int kz = 0; kz < K; ++kz)
                            acc[co][oz] = fmaf(r[oz + kz], wr[co][kz], acc[co][oz]);
            }
        }
    }

    if (active) {
#pragma unroll
        for (int co = 0; co < COUT; ++co) {
            float bv = bias[co];
#pragma unroll
            for (int oz = 0; oz < T; ++oz) {
                float v = acc[co][oz] + bv;
                y[((((((size_t)b * COUT + co) * T + ow) * T + ox) * T + oy) * T) + oz] =
                    v > 0.f ? v : 0.f;
            }
        }
    }
}

// ---------------------------------------------------------------------------
// Dense head: relu(h @ dw1.T + db1) @ dw2.T + db2 -> softmax over 2 classes.
//   h: [B,1280], dw1: [33,1280], dw2: [2,33], out: [B,2]
// One block per sample; warp-per-output for the 33-wide layer.
// ---------------------------------------------------------------------------
__global__ void dense_head(const float* __restrict__ h,
                           const float* __restrict__ dw1,
                           const float* __restrict__ db1,
                           const float* __restrict__ dw2,
                           const float* __restrict__ db2,
                           float* __restrict__ out)
{
    __shared__ float hb[1280];
    __shared__ float a[33];
    const int b   = blockIdx.x;
    const int tid = threadIdx.x;

    for (int i = tid; i < 1280; i += blockDim.x) hb[i] = h[b * 1280 + i];
    __syncthreads();

    const int warp = tid >> 5, lane = tid & 31;
    const int nwarps = blockDim.x >> 5;
    for (int co = warp; co < 33; co += nwarps) {
        float s = 0.f;
        for (int i = lane; i < 1280; i += 32) s += hb[i] * dw1[co * 1280 + i];
#pragma unroll
        for (int o = 16; o > 0; o >>= 1) s += __shfl_down_sync(0xffffffffu, s, o);
        if (lane == 0) {
            float v = s + db1[co];
            a[co] = v > 0.f ? v : 0.f;
        }
    }
    __syncthreads();

    if (tid == 0) {
        float z0 = db2[0], z1 = db2[1];
#pragma unroll
        for (int i = 0; i < 33; ++i) {
            z0 += a[i] * dw2[i];
            z1 += a[i] * dw2[33 + i];
        }
        float m  = fmaxf(z0, z1);
        float e0 = expf(z0 - m), e1 = expf(z1 - m);
        float inv = 1.f / (e0 + e1);
        out[2 * b]     = e0 * inv;
        out[2 * b + 1] = e1 * inv;
    }
}

// ---------------------------------------------------------------------------
// Launch
// ---------------------------------------------------------------------------
extern "C" void kernel_launch(void* const* d_in, const int* in_sizes, int n_in,
                              void* d_out, int out_size)
{
    const float* x   = (const float*)d_in[0];
    const float* w1  = (const float*)d_in[1];
    const float* b1  = (const float*)d_in[2];
    const float* w2  = (const float*)d_in[3];
    const float* b2  = (const float*)d_in[4];
    const float* w3  = (const float*)d_in[5];
    const float* b3  = (const float*)d_in[6];
    const float* w4  = (const float*)d_in[7];
    const float* b4  = (const float*)d_in[8];
    const float* w5  = (const float*)d_in[9];
    const float* b5  = (const float*)d_in[10];
    const float* dw1 = (const float*)d_in[11];
    const float* db1 = (const float*)d_in[12];
    const float* dw2 = (const float*)d_in[13];
    const float* db2 = (const float*)d_in[14];
    float* out = (float*)d_out;

    float *h1, *h2, *h3, *h4, *h5;
    cudaGetSymbolAddress((void**)&h1, g_h1);
    cudaGetSymbolAddress((void**)&h2, g_h2);
    cudaGetSymbolAddress((void**)&h3, g_h3);
    cudaGetSymbolAddress((void**)&h4, g_h4);
    cudaGetSymbolAddress((void**)&h5, g_h5);

    // smem bytes: weights + padded slab (one input channel)
    constexpr int sm1 = (3 * 1 * 256 + 4 * 18 * 18 * 19) * 4;  // 101568
    constexpr int sm2 = (3 * 3 * 256 + 4 * 15 * 15 * 15) * 4;  //  63216
    constexpr int sm3 = (4 * 3 * 256 + 4 * 12 * 12 * 13) * 4;  //  42240
    constexpr int sm4 = (5 * 4 * 256 + 4 * 9 * 9 * 9) * 4;     //  32144
    constexpr int sm5 = (5 * 5 * 81 + 3 * 6 * 6 * 7) * 4;      //  11124

    cudaFuncSetAttribute(conv4d_relu<18, 4, 1, 3>,
                         cudaFuncAttributeMaxDynamicSharedMemorySize, sm1);
    cudaFuncSetAttribute(conv4d_relu<15, 4, 3, 3>,
                         cudaFuncAttributeMaxDynamicSharedMemorySize, sm2);

    conv4d_relu<18, 4, 1, 3><<<256 * 15, 256, sm1>>>(x,  w1, b1, h1);
    conv4d_relu<15, 4, 3, 3><<<256 * 12, 160, sm2>>>(h1, w2, b2, h2);
    conv4d_relu<12, 4, 3, 4><<<256 * 9,   96, sm3>>>(h2, w3, b3, h3);
    conv4d_relu< 9, 4, 4, 5><<<256 * 6,   64, sm4>>>(h3, w4, b4, h4);
    conv4d_relu< 6, 3, 5, 5><<<256 * 4,   32, sm5>>>(h4, w5, b5, h5);
    dense_head<<<256, 256>>>(h5, dw1, db1, dw2, db2, out);
}